// round 6
// baseline (speedup 1.0000x reference)
#include <cuda_runtime.h>
#include <cuda_fp16.h>
#include <cstdint>

// ============================================================================
// SpikingMLP via fp16 split-product HMMA (mma.sync, sm_100 legacy path).
//   GEMM1: h = [xh|xm|xh] @ [w1h|w1h|w1m]^T  (logical K=2304)
//          physical storage deduped: A1=[xh|xm] (1536), W1=[w1h|w1m] (1536),
//          loader remaps columns (k>=MOD ? k-MOD : k).
//   LIF1 -> s1 (fp16 binary, stored once, K=3072)
//   GEMM2: y = [s1|s1] @ [w2h|w2m]^T (logical K=6144; A remap k>=3072 -> k-3072)
//   LIF2 -> out (fp32)
// GEMM: 128x128 tile, BK=64, 3-stage cp.async ring (ONE syncthreads/stage),
//       ldmatrix + mma.sync m16n8k16, XOR-swizzled smem.
// ============================================================================

#define MT 25088      // T*B*N = 4*32*196
#define MR 6272       // B*N
#define N1 3072
#define N2 768
#define KA1 1536      // physical A1 row stride
#define KB1 1536      // physical W1 row stride
#define KA2 3072      // physical s1 row stride
#define KB2 6144      // physical W2 row stride

__device__ __align__(128) __half g_A1[(size_t)MT * KA1];
__device__ __align__(128) __half g_W1[(size_t)N1 * KB1];
__device__ __align__(128) __half g_s1[(size_t)MT * KA2];
__device__ __align__(128) __half g_W2[(size_t)N2 * KB2];
__device__ __align__(128) float  g_h [(size_t)MT * N1];
__device__ __align__(128) float  g_y [(size_t)MT * N2];

// ---------------- helpers ----------------
__device__ __forceinline__ uint32_t smem_u32(const void* p) {
    uint32_t a;
    asm("{ .reg .u64 t; cvta.to.shared.u64 t, %1; cvt.u32.u64 %0, t; }" : "=r"(a) : "l"(p));
    return a;
}
__device__ __forceinline__ void cp_async16(uint32_t dst, const void* src) {
    asm volatile("cp.async.cg.shared.global [%0], [%1], 16;" :: "r"(dst), "l"(src) : "memory");
}
__device__ __forceinline__ void cp_commit() { asm volatile("cp.async.commit_group;" ::: "memory"); }
__device__ __forceinline__ void cp_wait1()  { asm volatile("cp.async.wait_group 1;" ::: "memory"); }
__device__ __forceinline__ void ldmx4(uint32_t* r, uint32_t addr) {
    asm volatile("ldmatrix.sync.aligned.m8n8.x4.shared.b16 {%0,%1,%2,%3}, [%4];"
                 : "=r"(r[0]), "=r"(r[1]), "=r"(r[2]), "=r"(r[3]) : "r"(addr));
}
__device__ __forceinline__ void mma16816(float* d, const uint32_t* a, uint32_t b0, uint32_t b1) {
    asm volatile(
        "mma.sync.aligned.m16n8k16.row.col.f32.f16.f16.f32 "
        "{%0,%1,%2,%3}, {%4,%5,%6,%7}, {%8,%9}, {%0,%1,%2,%3};"
        : "+f"(d[0]), "+f"(d[1]), "+f"(d[2]), "+f"(d[3])
        : "r"(a[0]), "r"(a[1]), "r"(a[2]), "r"(a[3]), "r"(b0), "r"(b1));
}
__device__ __forceinline__ uint32_t packh2(float a, float b) {
    __half2 h = __floats2half2_rn(a, b);
    return *(uint32_t*)&h;
}

// ---------------- GEMM: C[M,N] = A[M,Klog] @ B[N,Klog]^T with column remap ----
// MODA/MODB: logical col k maps to physical col k-MOD when k>=MOD (stage-aligned).
template<int MODA, int MODB>
__global__ __launch_bounds__(256, 2)
void hgemm_kernel(const __half* __restrict__ A, const __half* __restrict__ B,
                  float* __restrict__ C, int K, int N, int KaPhys, int KbPhys)
{
    extern __shared__ __align__(128) char smem_raw[];
    const uint32_t sbase = smem_u32(smem_raw);

    const int tid  = threadIdx.x;
    const int wid  = tid >> 5;
    const int lane = tid & 31;
    const int m0   = blockIdx.y * 128;
    const int n0   = blockIdx.x * 128;

    const int wm0 = (wid >> 1) * 32;     // warp m offset
    const int wn0 = (wid & 1) * 64;      // warp n offset

    const int lr = tid >> 3;             // loader row (+j*32)
    const int lc = tid & 7;              // 16B chunk

    float acc[2][8][4];
#pragma unroll
    for (int mi = 0; mi < 2; mi++)
#pragma unroll
        for (int j = 0; j < 8; j++)
#pragma unroll
            for (int r = 0; r < 4; r++) acc[mi][j][r] = 0.0f;

    const int S = K >> 6;

#define LOAD_STAGE(sidx)                                                            \
    do {                                                                            \
        const int k0_  = (sidx) << 6;                                               \
        const int ka0_ = (k0_ >= MODA) ? (k0_ - MODA) : k0_;                        \
        const int kb0_ = (k0_ >= MODB) ? (k0_ - MODB) : k0_;                        \
        const uint32_t Ad = sbase + (uint32_t)((sidx) % 3) * 32768u;                \
        const uint32_t Bd = Ad + 16384u;                                            \
        _Pragma("unroll")                                                           \
        for (int j = 0; j < 4; j++) {                                               \
            const int r_ = lr + j * 32;                                             \
            const uint32_t doff = (uint32_t)(r_ * 128 + ((lc ^ (r_ & 7)) << 4));    \
            cp_async16(Ad + doff,                                                   \
                       (const char*)(A + (size_t)(m0 + r_) * KaPhys + ka0_) + lc * 16); \
            cp_async16(Bd + doff,                                                   \
                       (const char*)(B + (size_t)(n0 + r_) * KbPhys + kb0_) + lc * 16); \
        }                                                                           \
    } while (0)

    LOAD_STAGE(0); cp_commit();
    LOAD_STAGE(1); cp_commit();

    // per-thread ldmatrix address bases
    const int g  = lane >> 3;
    const int r8 = lane & 7;
    int a_m[2]; uint32_t a_rowoff[2];
#pragma unroll
    for (int mi = 0; mi < 2; mi++) {
        a_m[mi] = wm0 + mi * 16 + (g & 1) * 8 + r8;
        a_rowoff[mi] = (uint32_t)(a_m[mi] * 128);
    }
    int b_n[4]; uint32_t b_rowoff[4];
#pragma unroll
    for (int p = 0; p < 4; p++) {
        b_n[p] = wn0 + p * 16 + (g >> 1) * 8 + r8;
        b_rowoff[p] = (uint32_t)(b_n[p] * 128);
    }

    for (int s = 0; s < S; s++) {
        cp_wait1();                 // stage s complete (one newer group may be in flight)
        __syncthreads();            // also guards buf (s+2)%3 == (s-1)%3 reuse
        if (s + 2 < S) LOAD_STAGE(s + 2);
        cp_commit();                // (possibly empty group — keeps wait semantics)

        const uint32_t Ab = sbase + (uint32_t)((s % 3) * 32768);
        const uint32_t Bb = Ab + 16384u;

#pragma unroll
        for (int ki = 0; ki < 4; ki++) {
            uint32_t af[2][4];
#pragma unroll
            for (int mi = 0; mi < 2; mi++) {
                const int c = 2 * ki + (g >> 1);
                ldmx4(af[mi], Ab + a_rowoff[mi] + (uint32_t)(((c ^ (a_m[mi] & 7)) << 4)));
            }
            uint32_t bf[4][4];
#pragma unroll
            for (int p = 0; p < 4; p++) {
                const int c = 2 * ki + (g & 1);
                ldmx4(bf[p], Bb + b_rowoff[p] + (uint32_t)(((c ^ (b_n[p] & 7)) << 4)));
            }
#pragma unroll
            for (int mi = 0; mi < 2; mi++)
#pragma unroll
                for (int p = 0; p < 4; p++) {
                    mma16816(acc[mi][2 * p],     af[mi], bf[p][0], bf[p][1]);
                    mma16816(acc[mi][2 * p + 1], af[mi], bf[p][2], bf[p][3]);
                }
        }
    }

    // epilogue
#pragma unroll
    for (int mi = 0; mi < 2; mi++) {
        const int row = m0 + wm0 + mi * 16 + (lane >> 2);
#pragma unroll
        for (int j = 0; j < 8; j++) {
            const int col = n0 + wn0 + j * 8 + (lane & 3) * 2;
            float* p0 = C + (size_t)row * N + col;
            *(float2*)p0 = make_float2(acc[mi][j][0], acc[mi][j][1]);
            float* p1 = p0 + (size_t)8 * N;
            *(float2*)p1 = make_float2(acc[mi][j][2], acc[mi][j][3]);
        }
    }
#undef LOAD_STAGE
}

// ---------------- split kernels ----------------
// x (fp32 [MT][768]) -> A1 fp16 [MT][1536] = [xh | xm]
__global__ void split_x_kernel(const float* __restrict__ x, __half* __restrict__ A1)
{
    int i = blockIdx.x * blockDim.x + threadIdx.x;
    if (i >= MT * 192) return;
    const int row = i / 192, col = (i % 192) * 4;
    float4 v = *(const float4*)(x + (size_t)row * 768 + col);
    float a[4] = {v.x, v.y, v.z, v.w};
    float hs[4], ms[4];
#pragma unroll
    for (int k = 0; k < 4; k++) {
        __half h = __float2half_rn(a[k]);
        hs[k] = __half2float(h);
        ms[k] = a[k] - hs[k];
    }
    uint2 ph = make_uint2(packh2(hs[0], hs[1]), packh2(hs[2], hs[3]));
    uint2 pm = make_uint2(packh2(ms[0], ms[1]), packh2(ms[2], ms[3]));
    __half* d = A1 + (size_t)row * KA1 + col;
    *(uint2*)d         = ph;
    *(uint2*)(d + 768) = pm;
}

// W1 (fp32 [3072][768]) -> W1 fp16 [3072][1536] = [w1h | w1m]
__global__ void split_w1_kernel(const float* __restrict__ w, __half* __restrict__ W1p)
{
    int i = blockIdx.x * blockDim.x + threadIdx.x;
    if (i >= N1 * 192) return;
    const int row = i / 192, col = (i % 192) * 4;
    float4 v = *(const float4*)(w + (size_t)row * 768 + col);
    float a[4] = {v.x, v.y, v.z, v.w};
    float hs[4], ms[4];
#pragma unroll
    for (int k = 0; k < 4; k++) {
        __half h = __float2half_rn(a[k]);
        hs[k] = __half2float(h);
        ms[k] = a[k] - hs[k];
    }
    uint2 ph = make_uint2(packh2(hs[0], hs[1]), packh2(hs[2], hs[3]));
    uint2 pm = make_uint2(packh2(ms[0], ms[1]), packh2(ms[2], ms[3]));
    __half* d = W1p + (size_t)row * KB1 + col;
    *(uint2*)d         = ph;
    *(uint2*)(d + 768) = pm;
}

// W2 (fp32 [768][3072]) -> W2 fp16 [768][6144] = [w2h | w2m]  (stacked, small)
__global__ void split_w2_kernel(const float* __restrict__ w, __half* __restrict__ W2p)
{
    int i = blockIdx.x * blockDim.x + threadIdx.x;
    if (i >= N2 * 768) return;
    const int row = i / 768, col = (i % 768) * 4;
    float4 v = *(const float4*)(w + (size_t)row * 3072 + col);
    float a[4] = {v.x, v.y, v.z, v.w};
    float hs[4], ms[4];
#pragma unroll
    for (int k = 0; k < 4; k++) {
        __half h = __float2half_rn(a[k]);
        hs[k] = __half2float(h);
        ms[k] = a[k] - hs[k];
    }
    uint2 ph = make_uint2(packh2(hs[0], hs[1]), packh2(hs[2], hs[3]));
    uint2 pm = make_uint2(packh2(ms[0], ms[1]), packh2(ms[2], ms[3]));
    __half* d = W2p + (size_t)row * KB2 + col;
    *(uint2*)d          = ph;
    *(uint2*)(d + 3072) = pm;
}

// ---------------- LIF kernels ----------------
// LIF1: h fp32 [t*MR+m][3072] -> s1 fp16 [t*MR+m][3072] (single copy)
__global__ void lif1_kernel(const float* __restrict__ h, const float* __restrict__ b1,
                            __half* __restrict__ s1)
{
    int i = blockIdx.x * blockDim.x + threadIdx.x;
    if (i >= MR * (N1 / 4)) return;
    const int m = i / (N1 / 4), col = (i % (N1 / 4)) * 4;
    const float4 bb = *(const float4*)(b1 + col);
    float v[4] = {0.f, 0.f, 0.f, 0.f};
#pragma unroll
    for (int t = 0; t < 4; t++) {
        const size_t row = (size_t)(t * MR + m);
        float4 hv = *(const float4*)(h + row * N1 + col);
        float hh[4] = {hv.x + bb.x, hv.y + bb.y, hv.z + bb.z, hv.w + bb.w};
        float s[4];
#pragma unroll
        for (int k = 0; k < 4; k++) {
            v[k] = v[k] + (hh[k] - v[k]) * 0.5f;
            s[k] = (v[k] >= 1.0f) ? 1.0f : 0.0f;
            v[k] = v[k] * (1.0f - s[k]);
        }
        *(uint2*)(s1 + row * KA2 + col) =
            make_uint2(packh2(s[0], s[1]), packh2(s[2], s[3]));
    }
}

// LIF2: y fp32 [t*MR+m][768] -> out fp32
__global__ void lif2_kernel(const float* __restrict__ y, const float* __restrict__ b2,
                            float* __restrict__ out)
{
    int i = blockIdx.x * blockDim.x + threadIdx.x;
    if (i >= MR * (N2 / 4)) return;
    const int m = i / (N2 / 4), col = (i % (N2 / 4)) * 4;
    const float4 bb = *(const float4*)(b2 + col);
    float v[4] = {0.f, 0.f, 0.f, 0.f};
#pragma unroll
    for (int t = 0; t < 4; t++) {
        const size_t row = (size_t)(t * MR + m);
        float4 yv = *(const float4*)(y + row * N2 + col);
        float hh[4] = {yv.x + bb.x, yv.y + bb.y, yv.z + bb.z, yv.w + bb.w};
        float s[4];
#pragma unroll
        for (int k = 0; k < 4; k++) {
            v[k] = v[k] + (hh[k] - v[k]) * 0.5f;
            s[k] = (v[k] >= 1.0f) ? 1.0f : 0.0f;
            v[k] = v[k] * (1.0f - s[k]);
        }
        *(float4*)(out + row * N2 + col) = make_float4(s[0], s[1], s[2], s[3]);
    }
}

// ---------------- host ----------------
extern "C" void kernel_launch(void* const* d_in, const int* in_sizes, int n_in,
                              void* d_out, int out_size)
{
    const float* x  = (const float*)d_in[0];
    const float* W1 = (const float*)d_in[1];
    const float* b1 = (const float*)d_in[2];
    const float* W2 = (const float*)d_in[3];
    const float* b2 = (const float*)d_in[4];
    float* out = (float*)d_out;

    __half *A1, *W1p, *s1, *W2p;
    float *h, *y;
    cudaGetSymbolAddress((void**)&A1,  g_A1);
    cudaGetSymbolAddress((void**)&W1p, g_W1);
    cudaGetSymbolAddress((void**)&s1,  g_s1);
    cudaGetSymbolAddress((void**)&W2p, g_W2);
    cudaGetSymbolAddress((void**)&h,   g_h);
    cudaGetSymbolAddress((void**)&y,   g_y);

    const int SMEM = 3 * 32768;   // 96KB 3-stage ring
    cudaFuncSetAttribute(hgemm_kernel<1536, 768>,
                         cudaFuncAttributeMaxDynamicSharedMemorySize, SMEM);
    cudaFuncSetAttribute(hgemm_kernel<3072, (1 << 30)>,
                         cudaFuncAttributeMaxDynamicSharedMemorySize, SMEM);

    // splits
    split_x_kernel<<<(MT * 192 + 255) / 256, 256>>>(x, A1);
    split_w1_kernel<<<(N1 * 192 + 255) / 256, 256>>>(W1, W1p);
    split_w2_kernel<<<(N2 * 768 + 255) / 256, 256>>>(W2, W2p);

    // GEMM1: h = [xh|xm|xh] @ [w1h|w1h|w1m]^T   (M=25088, N=3072, Klog=2304)
    {
        dim3 grid(N1 / 128, MT / 128);   // (24, 196)
        hgemm_kernel<1536, 768><<<grid, 256, SMEM>>>(A1, W1p, h, 2304, N1, KA1, KB1);
    }
    // LIF1 -> s1
    lif1_kernel<<<(MR * (N1 / 4) + 255) / 256, 256>>>(h, b1, s1);
    // GEMM2: y = [s1|s1] @ [w2h|w2m]^T   (M=25088, N=768, Klog=6144)
    {
        dim3 grid(N2 / 128, MT / 128);   // (6, 196)
        hgemm_kernel<3072, (1 << 30)><<<grid, 256, SMEM>>>(s1, W2p, y, 6144, N2, KA2, KB2);
    }
    // LIF2 -> out
    lif2_kernel<<<(MR * (N2 / 4) + 255) / 256, 256>>>(y, b2, out);
}